// round 11
// baseline (speedup 1.0000x reference)
#include <cuda_runtime.h>
#include <cuda_bf16.h>
#include <cstdint>

// Problem constants (fixed by the dataset)
#define T_TOK   16384
#define N_EXP   16
#define DIM     2048
#define CAP     2048
#define SLOTS   (N_EXP * CAP)           // 32768
#define OUT_MAIN ((size_t)SLOTS * DIM)  // 67,108,864 floats
#define ROW4    (DIM / 4)               // 512 float4 per row

#define CHUNKS  64
#define CHTOK   256                     // tokens per index chunk (== blockDim)
#define FILLB   (N_EXP * 8)             // 128 fill helper blocks in scatter grid

// Device scratch (no allocs allowed)
__device__ int   g_cnt[N_EXP * CHUNKS];   // per-expert per-chunk hit counts
__device__ int   g_load[N_EXP];           // capacity-clipped loads
__device__ int   g_dst[T_TOK * 2];        // per-token destination slots (-1 = dropped)
__device__ float g_gt [T_TOK * 2];        // per-token gate scores
__device__ unsigned g_arrive;             // arrive/depart barrier word

// ---------------------------------------------------------------------------
// Kernel 1: fused count + scan + dest. 64 blocks x 256 threads.
// All 64 blocks co-resident (64 < 148 SMs) -> internal spin barrier is safe.
// Publishes g_dst/g_gt/g_load, then triggers programmatic launch completion
// so the PDL-launched scatter can pass its griddepcontrol.wait early.
// ---------------------------------------------------------------------------
__global__ __launch_bounds__(CHTOK)
void idx_kernel(const int4* __restrict__ hm4, const float4* __restrict__ sc4,
                float* __restrict__ out, long long out_size)
{
    const int c    = blockIdx.x;
    const int tid  = threadIdx.x;
    const int lane = tid & 31;
    const int wid  = tid >> 5;            // 0..7
    const int t    = c * CHTOK + tid;
    const unsigned lt = (1u << lane) - 1u;

    int4   m[4];
    float4 s[4];
    #pragma unroll
    for (int i = 0; i < 4; i++) {
        m[i] = hm4[(size_t)t * 4 + i];
        s[i] = sc4[(size_t)t * 4 + i];
    }
    const int*   v  = (const int*)m;
    const float* sv = (const float*)s;

    unsigned bits = 0;
    #pragma unroll
    for (int e = 0; e < N_EXP; e++) bits |= (v[e] > 0 ? 1u : 0u) << e;

    __shared__ int s_cnt[8][N_EXP];
    __shared__ int s_off[N_EXP];

    int      k = 0;
    int      e_sel[2] = {-1, -1};
    unsigned b_sel[2] = {0, 0};
    #pragma unroll
    for (int e = 0; e < N_EXP; e++) {
        unsigned ball = __ballot_sync(0xffffffffu, (bits >> e) & 1u);
        if (lane == 0) s_cnt[wid][e] = __popc(ball);
        if (((bits >> e) & 1u) && k < 2) { e_sel[k] = e; b_sel[k] = ball; k++; }
    }
    __syncthreads();

    if (tid < N_EXP) {
        int sum = 0;
        #pragma unroll
        for (int w = 0; w < 8; w++) sum += s_cnt[w][tid];
        g_cnt[tid * CHUNKS + c] = sum;
    }
    __threadfence();
    __syncthreads();

    // ---- co-resident barrier: low 16 bits = arrivals, high 16 = departures.
    // Last block out resets the word for the next graph replay (proven R10).
    if (tid == 0) {
        atomicAdd(&g_arrive, 1u);
        volatile unsigned* p = &g_arrive;
        while ((*p & 0xFFFFu) < CHUNKS) __nanosleep(40);
        unsigned prev = atomicAdd(&g_arrive, 0x10000u);
        if ((prev >> 16) == CHUNKS - 1)
            atomicExch(&g_arrive, 0u);
    }
    __syncthreads();

    // exclusive chunk offsets: expert = tid>>4, segment = tid&15 (4 chunks each)
    {
        const int e   = tid >> 4;
        const int seg = tid & 15;
        int partial = 0;
        #pragma unroll
        for (int i = 0; i < 4; i++) {
            const int cc = seg * 4 + i;
            if (cc < c) partial += __ldcg(&g_cnt[e * CHUNKS + cc]);
        }
        #pragma unroll
        for (int o = 8; o >= 1; o >>= 1)
            partial += __shfl_down_sync(0xffffffffu, partial, o, 16);
        if (seg == 0) s_off[e] = partial;
    }
    __syncthreads();

    // last chunk block owns the totals -> loads
    if (c == CHUNKS - 1 && tid < N_EXP) {
        int tot = s_off[tid];
        #pragma unroll
        for (int w = 0; w < 8; w++) tot += s_cnt[w][tid];
        const int load = tot < CAP ? tot : CAP;
        g_load[tid] = load;
        if (out_size >= (long long)(OUT_MAIN + N_EXP))
            out[OUT_MAIN + tid] = (float)load;
    }

    // per-token destinations
    #pragma unroll
    for (int j = 0; j < 2; j++) {
        int dst = -1;
        float g = 0.0f;
        if (j < k) {
            const int e = e_sel[j];
            int woff = 0;
            #pragma unroll
            for (int w = 0; w < 8; w++) if (w < wid) woff += s_cnt[w][e];
            const int pos = s_off[e] + woff + __popc(b_sel[j] & lt);
            if (pos < CAP) dst = e * CAP + pos;
            g = sv[e];
        }
        g_dst[t * 2 + j] = dst;
        g_gt [t * 2 + j] = g;
    }

    // Publish results, then release PDL dependents early.
    __threadfence();
    __syncthreads();
    cudaTriggerProgrammaticLaunchCompletion();
}

// ---------------------------------------------------------------------------
// Kernel 2: fused fill + token-major scatter, PDL-launched.
// Token blocks issue their 8KB row loads BEFORE griddepcontrol.wait, hiding
// the idx kernel + launch gap under their own DRAM latency.
// ---------------------------------------------------------------------------
__global__ __launch_bounds__(256, 8)
void scatter_kernel(const float4* __restrict__ in_flow, float4* __restrict__ out)
{
    const int tid = threadIdx.x;

    if (blockIdx.x < FILLB) {
        const int f = blockIdx.x;
        const int e = f >> 3;
        const int y = f & 7;
        cudaGridDependencySynchronize();
        const int load = __ldcg(&g_load[e]);
        const float4 z = make_float4(0.f, 0.f, 0.f, 0.f);
        for (int r = load + y; r < CAP; r += 8) {
            float4* o = out + (size_t)(e * CAP + r) * ROW4;
            __stcs(o + tid, z);
            __stcs(o + tid + 256, z);
        }
        return;
    }

    const int t = blockIdx.x - FILLB;

    // Issue the streaming row read first — overlaps with the idx dependency.
    const float4* __restrict__ r = in_flow + (size_t)t * ROW4;
    float4 a = __ldcs(r + tid);
    float4 b = __ldcs(r + tid + 256);

    cudaGridDependencySynchronize();

    const int d0 = __ldcg(&g_dst[t * 2 + 0]);
    const int d1 = __ldcg(&g_dst[t * 2 + 1]);
    if (d0 < 0 && d1 < 0) return;

    const float g0 = __ldcg(&g_gt[t * 2 + 0]);
    const float g1 = __ldcg(&g_gt[t * 2 + 1]);

    if (d0 >= 0) {
        float4* o = out + (size_t)d0 * ROW4;
        __stcs(o + tid,       make_float4(a.x * g0, a.y * g0, a.z * g0, a.w * g0));
        __stcs(o + tid + 256, make_float4(b.x * g0, b.y * g0, b.z * g0, b.w * g0));
    }
    if (d1 >= 0) {
        float4* o = out + (size_t)d1 * ROW4;
        __stcs(o + tid,       make_float4(a.x * g1, a.y * g1, a.z * g1, a.w * g1));
        __stcs(o + tid + 256, make_float4(b.x * g1, b.y * g1, b.z * g1, b.w * g1));
    }
}

extern "C" void kernel_launch(void* const* d_in, const int* in_sizes, int n_in,
                              void* d_out, int out_size)
{
    const float* in_flow  = (const float*)d_in[0];   // [T, D] f32
    const int*   hot_mask = (const int*)  d_in[1];   // [T, E] i32
    const float* score    = (const float*)d_in[2];   // [T, E] f32
    float*       out      = (float*)d_out;

    idx_kernel<<<CHUNKS, CHTOK>>>((const int4*)hot_mask, (const float4*)score,
                                  out, (long long)out_size);

    // PDL launch of the scatter: may start while idx_kernel runs; the device-
    // side griddepcontrol.wait enforces the dependency with HW guarantees.
    cudaLaunchConfig_t cfg = {};
    cfg.gridDim  = dim3(T_TOK + FILLB, 1, 1);
    cfg.blockDim = dim3(256, 1, 1);
    cudaLaunchAttribute attr[1];
    attr[0].id = cudaLaunchAttributeProgrammaticStreamSerialization;
    attr[0].val.programmaticStreamSerializationAllowed = 1;
    cfg.attrs    = attr;
    cfg.numAttrs = 1;
    cudaError_t err = cudaLaunchKernelEx(&cfg, scatter_kernel,
                                         (const float4*)in_flow, (float4*)out);
    if (err != cudaSuccess) {
        // Fallback: plain ordered launch (R10 semantics, still correct).
        scatter_kernel<<<T_TOK + FILLB, 256>>>((const float4*)in_flow,
                                               (float4*)out);
    }
}

// round 12
// speedup vs baseline: 1.0608x; 1.0608x over previous
#include <cuda_runtime.h>
#include <cuda_bf16.h>
#include <cstdint>

// Problem constants (fixed by the dataset)
#define T_TOK   16384
#define N_EXP   16
#define DIM     2048
#define CAP     2048
#define SLOTS   (N_EXP * CAP)           // 32768
#define OUT_MAIN ((size_t)SLOTS * DIM)  // 67,108,864 floats
#define ROW4    (DIM / 4)               // 512 float4 per row

#define CHUNKS  64
#define CHTOK   256                     // tokens per index chunk (== blockDim)
#define FILLB   (N_EXP * 8)             // 128 fill helper blocks in scatter grid

// Device scratch (no allocs allowed)
__device__ int   g_cnt [N_EXP * CHUNKS];  // per-expert per-chunk hit counts (4KB, L2-hot)
__device__ int   g_meta[T_TOK];           // per-token packed: 2 x 16b halves (rank<<4)|e, 0xFFFF=none
__device__ float g_gt  [T_TOK * 2];       // per-token gate scores

// ---------------------------------------------------------------------------
// Kernel 1: single-pass count + chunk-local rank. 64 blocks x 256 threads.
// NO inter-block synchronization anywhere — global offsets are resolved by
// the consumers from g_cnt.
// ---------------------------------------------------------------------------
__global__ __launch_bounds__(CHTOK)
void idx_kernel(const int4* __restrict__ hm4, const float4* __restrict__ sc4)
{
    const int c    = blockIdx.x;
    const int tid  = threadIdx.x;
    const int lane = tid & 31;
    const int wid  = tid >> 5;            // 0..7
    const int t    = c * CHTOK + tid;
    const unsigned lt = (1u << lane) - 1u;

    int4   m[4];
    float4 s[4];
    #pragma unroll
    for (int i = 0; i < 4; i++) {
        m[i] = hm4[(size_t)t * 4 + i];
        s[i] = sc4[(size_t)t * 4 + i];
    }
    const int*   v  = (const int*)m;
    const float* sv = (const float*)s;

    unsigned bits = 0;
    #pragma unroll
    for (int e = 0; e < N_EXP; e++) bits |= (v[e] > 0 ? 1u : 0u) << e;

    __shared__ int s_cnt[8][N_EXP];

    int      k = 0;
    int      e_sel[2] = {-1, -1};
    unsigned b_sel[2] = {0, 0};
    #pragma unroll
    for (int e = 0; e < N_EXP; e++) {
        unsigned ball = __ballot_sync(0xffffffffu, (bits >> e) & 1u);
        if (lane == 0) s_cnt[wid][e] = __popc(ball);
        if (((bits >> e) & 1u) && k < 2) { e_sel[k] = e; b_sel[k] = ball; k++; }
    }
    __syncthreads();

    if (tid < N_EXP) {
        int sum = 0;
        #pragma unroll
        for (int w = 0; w < 8; w++) sum += s_cnt[w][tid];
        g_cnt[tid * CHUNKS + c] = sum;
    }

    // per-token chunk-local rank, packed into 2 x 16 bits
    unsigned meta = 0xFFFFFFFFu;
    #pragma unroll
    for (int j = 0; j < 2; j++) {
        unsigned h = 0xFFFFu;
        float g = 0.0f;
        if (j < k) {
            const int e = e_sel[j];
            int woff = 0;
            #pragma unroll
            for (int w = 0; w < 8; w++) if (w < wid) woff += s_cnt[w][e];
            const int rank = woff + __popc(b_sel[j] & lt);   // < 256
            h = ((unsigned)rank << 4) | (unsigned)e;
            g = sv[e];
        }
        meta = (meta & ~(0xFFFFu << (16 * j))) | (h << (16 * j));
        g_gt[t * 2 + j] = g;
    }
    g_meta[t] = (int)meta;
}

// ---------------------------------------------------------------------------
// Kernel 2: fused fill + token-major scatter, PDL-launched.
// Token blocks: issue 8KB row loads first, then resolve their own global
// offset from the L2-hot g_cnt table (2 warps, one per expert assignment).
// Fill blocks: reduce per-expert totals -> load, zero tails, emit loads.
// ---------------------------------------------------------------------------
__global__ __launch_bounds__(256, 8)
void scatter_kernel(const float4* __restrict__ in_flow, float4* __restrict__ out4,
                    float* __restrict__ out, long long out_size)
{
    const int tid = threadIdx.x;

    if (blockIdx.x < FILLB) {
        const int f = blockIdx.x;
        const int e = f >> 3;
        const int y = f & 7;
        cudaGridDependencySynchronize();

        __shared__ int s_load;
        if (tid < 32) {
            int part = __ldcg(&g_cnt[e * CHUNKS + tid]) +
                       __ldcg(&g_cnt[e * CHUNKS + tid + 32]);
            #pragma unroll
            for (int o = 16; o >= 1; o >>= 1)
                part += __shfl_down_sync(0xffffffffu, part, o);
            if (tid == 0) {
                const int load = part < CAP ? part : CAP;
                s_load = load;
                if (y == 0 && out_size >= (long long)(OUT_MAIN + N_EXP))
                    out[OUT_MAIN + e] = (float)load;
            }
        }
        __syncthreads();
        const int load = s_load;
        const float4 z = make_float4(0.f, 0.f, 0.f, 0.f);
        for (int r = load + y; r < CAP; r += 8) {
            float4* o = out4 + (size_t)(e * CAP + r) * ROW4;
            __stcs(o + tid, z);
            __stcs(o + tid + 256, z);
        }
        return;
    }

    const int t = blockIdx.x - FILLB;
    const int c = t >> 8;                 // CHTOK = 256

    // Issue the streaming row read first — overlaps the PDL dependency and
    // the offset resolution below.
    const float4* __restrict__ r = in_flow + (size_t)t * ROW4;
    float4 a = __ldcs(r + tid);
    float4 b = __ldcs(r + tid + 256);

    cudaGridDependencySynchronize();

    __shared__ int s_dst[2];
    const int meta = __ldcg(&g_meta[t]);

    if (tid < 64) {
        const int j    = tid >> 5;        // assignment 0 / 1
        const int lane = tid & 31;
        const unsigned h = ((unsigned)meta >> (16 * j)) & 0xFFFFu;
        int dst = -1;
        if (h != 0xFFFFu) {
            const int e    = (int)(h & 15u);
            const int rank = (int)(h >> 4);
            int part = 0;
            if (lane < c)      part += __ldcg(&g_cnt[e * CHUNKS + lane]);
            if (lane + 32 < c) part += __ldcg(&g_cnt[e * CHUNKS + lane + 32]);
            #pragma unroll
            for (int o = 16; o >= 1; o >>= 1)
                part += __shfl_down_sync(0xffffffffu, part, o);
            if (lane == 0) {
                const int pos = part + rank;
                if (pos < CAP) dst = e * CAP + pos;
            }
        }
        if (lane == 0) s_dst[j] = dst;
    }
    __syncthreads();

    const int d0 = s_dst[0];
    const int d1 = s_dst[1];
    if (d0 < 0 && d1 < 0) return;

    const float g0 = __ldcg(&g_gt[t * 2 + 0]);
    const float g1 = __ldcg(&g_gt[t * 2 + 1]);

    if (d0 >= 0) {
        float4* o = out4 + (size_t)d0 * ROW4;
        __stcs(o + tid,       make_float4(a.x * g0, a.y * g0, a.z * g0, a.w * g0));
        __stcs(o + tid + 256, make_float4(b.x * g0, b.y * g0, b.z * g0, b.w * g0));
    }
    if (d1 >= 0) {
        float4* o = out4 + (size_t)d1 * ROW4;
        __stcs(o + tid,       make_float4(a.x * g1, a.y * g1, a.z * g1, a.w * g1));
        __stcs(o + tid + 256, make_float4(b.x * g1, b.y * g1, b.z * g1, b.w * g1));
    }
}

extern "C" void kernel_launch(void* const* d_in, const int* in_sizes, int n_in,
                              void* d_out, int out_size)
{
    const float* in_flow  = (const float*)d_in[0];   // [T, D] f32
    const int*   hot_mask = (const int*)  d_in[1];   // [T, E] i32
    const float* score    = (const float*)d_in[2];   // [T, E] f32
    float*       out      = (float*)d_out;

    idx_kernel<<<CHUNKS, CHTOK>>>((const int4*)hot_mask, (const float4*)score);

    // PDL launch: scatter grid comes up while idx drains; device-side
    // griddepcontrol.wait enforces the dependency with HW guarantees.
    cudaLaunchConfig_t cfg = {};
    cfg.gridDim  = dim3(T_TOK + FILLB, 1, 1);
    cfg.blockDim = dim3(256, 1, 1);
    cudaLaunchAttribute attr[1];
    attr[0].id = cudaLaunchAttributeProgrammaticStreamSerialization;
    attr[0].val.programmaticStreamSerializationAllowed = 1;
    cfg.attrs    = attr;
    cfg.numAttrs = 1;
    cudaError_t err = cudaLaunchKernelEx(&cfg, scatter_kernel,
                                         (const float4*)in_flow, (float4*)out,
                                         out, (long long)out_size);
    if (err != cudaSuccess) {
        // Fallback: plain ordered launch (still correct).
        scatter_kernel<<<T_TOK + FILLB, 256>>>((const float4*)in_flow,
                                               (float4*)out, out,
                                               (long long)out_size);
    }
}

// round 13
// speedup vs baseline: 1.0664x; 1.0053x over previous
#include <cuda_runtime.h>
#include <cuda_bf16.h>
#include <cstdint>

// Problem constants (fixed by the dataset)
#define T_TOK   16384
#define N_EXP   16
#define DIM     2048
#define CAP     2048
#define SLOTS   (N_EXP * CAP)           // 32768
#define OUT_MAIN ((size_t)SLOTS * DIM)  // 67,108,864 floats
#define ROW4    (DIM / 4)               // 512 float4 per row

#define CHUNKS  128
#define CHTOK   128                     // tokens per index chunk (== idx blockDim)
#define FILLB   (N_EXP * 8)             // 128 fill helper blocks in scatter grid

// Device scratch (no allocs allowed)
__device__ int g_cnt [N_EXP * CHUNKS];  // per-expert per-chunk hit counts (8KB, L2-hot)
__device__ int g_meta[T_TOK];           // per-token packed: 2 x 16b halves (rank<<4)|e, 0xFFFF=none

// ---------------------------------------------------------------------------
// Kernel 1: single-pass count + chunk-local rank. 128 blocks x 128 threads.
// Mask only — no score traffic. No inter-block synchronization.
// ---------------------------------------------------------------------------
__global__ __launch_bounds__(CHTOK)
void idx_kernel(const int4* __restrict__ hm4)
{
    const int c    = blockIdx.x;
    const int tid  = threadIdx.x;
    const int lane = tid & 31;
    const int wid  = tid >> 5;            // 0..3
    const int t    = c * CHTOK + tid;
    const unsigned lt = (1u << lane) - 1u;

    int4 m[4];
    #pragma unroll
    for (int i = 0; i < 4; i++) m[i] = hm4[(size_t)t * 4 + i];
    const int* v = (const int*)m;

    unsigned bits = 0;
    #pragma unroll
    for (int e = 0; e < N_EXP; e++) bits |= (v[e] > 0 ? 1u : 0u) << e;

    __shared__ int s_cnt[4][N_EXP];

    int      k = 0;
    int      e_sel[2] = {-1, -1};
    unsigned b_sel[2] = {0, 0};
    #pragma unroll
    for (int e = 0; e < N_EXP; e++) {
        unsigned ball = __ballot_sync(0xffffffffu, (bits >> e) & 1u);
        if (lane == 0) s_cnt[wid][e] = __popc(ball);
        if (((bits >> e) & 1u) && k < 2) { e_sel[k] = e; b_sel[k] = ball; k++; }
    }
    __syncthreads();

    if (tid < N_EXP)
        g_cnt[tid * CHUNKS + c] =
            s_cnt[0][tid] + s_cnt[1][tid] + s_cnt[2][tid] + s_cnt[3][tid];

    // per-token chunk-local rank, packed into 2 x 16 bits
    unsigned meta = 0xFFFFFFFFu;
    #pragma unroll
    for (int j = 0; j < 2; j++) {
        unsigned h = 0xFFFFu;
        if (j < k) {
            const int e = e_sel[j];
            int woff = 0;
            #pragma unroll
            for (int w = 0; w < 4; w++) if (w < wid) woff += s_cnt[w][e];
            const int rank = woff + __popc(b_sel[j] & lt);   // < 128
            h = ((unsigned)rank << 4) | (unsigned)e;
        }
        meta = (meta & ~(0xFFFFu << (16 * j))) | (h << (16 * j));
    }
    g_meta[t] = (int)meta;

    // Release PDL dependents as soon as every idx CTA has reached this point.
    __threadfence();
    cudaTriggerProgrammaticLaunchCompletion();
}

// ---------------------------------------------------------------------------
// Kernel 2: fused fill + token-major scatter, PDL-launched.
// Token blocks: issue 8KB row loads first, then resolve their own global
// offset from the L2-hot g_cnt table (2 warps, one per assignment) and read
// their gates straight from score.
// Fill blocks: reduce per-expert totals -> load, zero tails, emit loads.
// ---------------------------------------------------------------------------
__global__ __launch_bounds__(256, 8)
void scatter_kernel(const float4* __restrict__ in_flow,
                    const float*  __restrict__ score,
                    float4* __restrict__ out4,
                    float*  __restrict__ out, long long out_size)
{
    const int tid = threadIdx.x;

    if (blockIdx.x < FILLB) {
        const int f = blockIdx.x;
        const int e = f >> 3;
        const int y = f & 7;
        cudaGridDependencySynchronize();

        __shared__ int s_load;
        if (tid < 32) {
            int part = 0;
            #pragma unroll
            for (int i = 0; i < 4; i++)
                part += __ldcg(&g_cnt[e * CHUNKS + i * 32 + tid]);
            #pragma unroll
            for (int o = 16; o >= 1; o >>= 1)
                part += __shfl_down_sync(0xffffffffu, part, o);
            if (tid == 0) {
                const int load = part < CAP ? part : CAP;
                s_load = load;
                if (y == 0 && out_size >= (long long)(OUT_MAIN + N_EXP))
                    out[OUT_MAIN + e] = (float)load;
            }
        }
        __syncthreads();
        const int load = s_load;
        const float4 z = make_float4(0.f, 0.f, 0.f, 0.f);
        for (int r = load + y; r < CAP; r += 8) {
            float4* o = out4 + (size_t)(e * CAP + r) * ROW4;
            __stcs(o + tid, z);
            __stcs(o + tid + 256, z);
        }
        return;
    }

    const int t = blockIdx.x - FILLB;
    const int c = t >> 7;                 // CHTOK = 128

    // Issue the streaming row read first — overlaps the PDL dependency and
    // the offset resolution below.
    const float4* __restrict__ r = in_flow + (size_t)t * ROW4;
    float4 a = __ldcs(r + tid);
    float4 b = __ldcs(r + tid + 256);

    cudaGridDependencySynchronize();

    __shared__ int   s_dst[2];
    __shared__ float s_g[2];
    const int meta = __ldcg(&g_meta[t]);

    if (tid < 64) {
        const int j    = tid >> 5;        // assignment 0 / 1
        const int lane = tid & 31;
        const unsigned h = ((unsigned)meta >> (16 * j)) & 0xFFFFu;
        int   dst = -1;
        float g   = 0.0f;
        if (h != 0xFFFFu) {
            const int e    = (int)(h & 15u);
            const int rank = (int)(h >> 4);
            int part = 0;
            #pragma unroll
            for (int i = 0; i < 4; i++) {
                const int cc = i * 32 + lane;
                if (cc < c) part += __ldcg(&g_cnt[e * CHUNKS + cc]);
            }
            #pragma unroll
            for (int o = 16; o >= 1; o >>= 1)
                part += __shfl_down_sync(0xffffffffu, part, o);
            if (lane == 0) {
                const int pos = part + rank;
                if (pos < CAP) dst = e * CAP + pos;
                g = __ldg(&score[t * N_EXP + e]);
            }
        }
        if (lane == 0) { s_dst[j] = dst; s_g[j] = g; }
    }
    __syncthreads();

    const int d0 = s_dst[0];
    const int d1 = s_dst[1];
    if (d0 < 0 && d1 < 0) return;

    const float g0 = s_g[0];
    const float g1 = s_g[1];

    if (d0 >= 0) {
        float4* o = out4 + (size_t)d0 * ROW4;
        __stcs(o + tid,       make_float4(a.x * g0, a.y * g0, a.z * g0, a.w * g0));
        __stcs(o + tid + 256, make_float4(b.x * g0, b.y * g0, b.z * g0, b.w * g0));
    }
    if (d1 >= 0) {
        float4* o = out4 + (size_t)d1 * ROW4;
        __stcs(o + tid,       make_float4(a.x * g1, a.y * g1, a.z * g1, a.w * g1));
        __stcs(o + tid + 256, make_float4(b.x * g1, b.y * g1, b.z * g1, b.w * g1));
    }
}

extern "C" void kernel_launch(void* const* d_in, const int* in_sizes, int n_in,
                              void* d_out, int out_size)
{
    const float* in_flow  = (const float*)d_in[0];   // [T, D] f32
    const int*   hot_mask = (const int*)  d_in[1];   // [T, E] i32
    const float* score    = (const float*)d_in[2];   // [T, E] f32
    float*       out      = (float*)d_out;

    idx_kernel<<<CHUNKS, CHTOK>>>((const int4*)hot_mask);

    // PDL launch: scatter grid comes up while idx drains; device-side
    // griddepcontrol.wait enforces the dependency with HW guarantees.
    cudaLaunchConfig_t cfg = {};
    cfg.gridDim  = dim3(T_TOK + FILLB, 1, 1);
    cfg.blockDim = dim3(256, 1, 1);
    cudaLaunchAttribute attr[1];
    attr[0].id = cudaLaunchAttributeProgrammaticStreamSerialization;
    attr[0].val.programmaticStreamSerializationAllowed = 1;
    cfg.attrs    = attr;
    cfg.numAttrs = 1;
    cudaError_t err = cudaLaunchKernelEx(&cfg, scatter_kernel,
                                         (const float4*)in_flow, score,
                                         (float4*)out, out, (long long)out_size);
    if (err != cudaSuccess) {
        // Fallback: plain ordered launch (still correct).
        scatter_kernel<<<T_TOK + FILLB, 256>>>((const float4*)in_flow, score,
                                               (float4*)out, out,
                                               (long long)out_size);
    }
}